// round 14
// baseline (speedup 1.0000x reference)
#include <cuda_runtime.h>
#include <cuda_bf16.h>
#include <cstdint>

// Problem constants
#define NN   4096
#define PP   32768
#define EE   4096
#define DD   128
#define RR   4
#define KK   16
#define NW   128       // 4096 bits / 32 words per adjacency row

// ---- K1 striping: group of 3 = 2 pack rows + 1 gather block; +1 tail ----
#define GRID_1  (2048 * 3 + 1)

// ---------------- device scratch ----------------
__device__ unsigned       g_bits  [NN * NW];
__device__ float          g_C     [NN];
__device__ float          g_invden[NN];
__device__ __nv_bfloat16  g_embh  [NN * DD];      // bf16 copy of emb
__device__ __nv_bfloat16  g_projh [NN * DD];      // bf16 proj
__device__ __nv_bfloat16  g_epsh  [NN * DD];      // bf16 eps
__device__ float          g_hbar  [NN * RR * DD]; // fp32 h_bar
__device__ float          g_alpha;

// ---------------- helpers ----------------
__device__ __forceinline__ unsigned long long pk(float x, float y) {
    unsigned long long r;
    asm("mov.b64 %0, {%1, %2};" : "=l"(r) : "f"(x), "f"(y));
    return r;
}
__device__ __forceinline__ void upk(float& x, float& y, unsigned long long v) {
    asm("mov.b64 {%0, %1}, %2;" : "=f"(x), "=f"(y) : "l"(v));
}
__device__ __forceinline__ void ffma2(unsigned long long& d,
                                      unsigned long long a,
                                      unsigned long long b) {
    asm("fma.rn.f32x2 %0, %1, %2, %0;" : "+l"(d) : "l"(a), "l"(b));
}
__device__ __forceinline__ float2 bcvt(unsigned u) {
    __nv_bfloat162 h = *reinterpret_cast<__nv_bfloat162*>(&u);
    return __bfloat1622float2(h);
}

// =======================================================================
// K0: emb (fp32) -> g_embh (bf16), 8 floats per thread
// =======================================================================
__global__ void __launch_bounds__(256)
k_0(const float* __restrict__ emb) {
    int t = blockIdx.x * 256 + threadIdx.x;      // 65536 threads
    const float4* src = (const float4*)emb;
    float4 a = src[t * 2];
    float4 b = src[t * 2 + 1];
    __nv_bfloat162* dst = (__nv_bfloat162*)g_embh;
    dst[t * 4 + 0] = __floats2bfloat162_rn(a.x, a.y);
    dst[t * 4 + 1] = __floats2bfloat162_rn(a.z, a.w);
    dst[t * 4 + 2] = __floats2bfloat162_rn(b.x, b.y);
    dst[t * 4 + 3] = __floats2bfloat162_rn(b.z, b.w);
}

// =======================================================================
// K1: pack | gather(bf16 emb) | alpha, striped
// =======================================================================
__global__ void __launch_bounds__(256)
k_1(const int*   __restrict__ adj,
    const int*   __restrict__ nidx,
    const float* __restrict__ tev,
    const float* __restrict__ theta_p) {
    __shared__ int   sdeg[8];
    __shared__ float sw[8];

    int b    = blockIdx.x;
    int tid  = threadIdx.x;
    int lane = tid & 31, w = tid >> 5;

    if (b < 2048 * 3) {
        int r = b % 3, q = b / 3;
        if (r < 2) {
            int row = q * 2 + r;
            const int* a = adj + (size_t)row * NN;
            int v[16];
            #pragma unroll
            for (int i = 0; i < 16; i++)
                v[i] = a[(w * 16 + i) * 32 + lane];
            unsigned keep = 0;
            #pragma unroll
            for (int i = 0; i < 16; i++) {
                unsigned m = __ballot_sync(0xffffffffu, v[i] != 0);
                if (lane == i) keep = m;
            }
            if (lane < 16)
                g_bits[row * NW + w * 16 + lane] = keep;
            int dsum = (lane < 16) ? __popc(keep) : 0;
            #pragma unroll
            for (int o = 16; o; o >>= 1)
                dsum += __shfl_down_sync(0xffffffffu, dsum, o);
            if (lane == 0) sdeg[w] = dsum;
            __syncthreads();
            if (tid == 0) {
                int s = 0;
                #pragma unroll
                for (int i = 0; i < 8; i++) s += sdeg[i];
                float d   = (float)s;
                float den = d * (d - 1.0f);
                if (den == 0.0f) den = 1e-6f;
                g_invden[row] = 2.0f / den;
            }
        } else {
            // ---- gather from bf16 emb: warp per (node,r) unit ----
            int unit = q * 8 + w;
            const uint2* e2 = (const uint2*)g_embh;   // 8B/lane = 4 dims
            int nid = 0;
            if (lane < KK) nid = nidx[unit * KK + lane];
            float4 acc = make_float4(0.f, 0.f, 0.f, 0.f);
            #pragma unroll
            for (int k = 0; k < KK; k++) {
                int id = __shfl_sync(0xffffffffu, nid, k);
                uint2 v = __ldg(&e2[id * 32 + lane]);
                float2 lo = bcvt(v.x), hi = bcvt(v.y);
                acc.x += lo.x; acc.y += lo.y; acc.z += hi.x; acc.w += hi.y;
            }
            ((float4*)g_hbar)[unit * 32 + lane] =
                make_float4(acc.x * 0.0625f, acc.y * 0.0625f,
                            acc.z * 0.0625f, acc.w * 0.0625f);
        }
    } else {
        float th = theta_p[0];
        float s  = 0.f;
        for (int i = tid; i < EE; i += 256)
            s += expf(-th * (1.0f - tev[i]));
        #pragma unroll
        for (int o = 16; o; o >>= 1) s += __shfl_down_sync(0xffffffffu, s, o);
        if (lane == 0) sw[w] = s;
        __syncthreads();
        if (tid == 0) {
            float tot = 0.f;
            #pragma unroll
            for (int i = 0; i < 8; i++) tot += sw[i];
            g_alpha = tot;
        }
    }
}

// =======================================================================
// K2a: tri — 2 rows/block, 4 warps/row, contiguous MLP-8 chunks
// =======================================================================
__global__ void __launch_bounds__(256)
k_tri() {
    __shared__ __align__(16) unsigned sri[2][NW];
    __shared__ int  list[2][192];
    __shared__ int  warpsum[8], warpbase[8];
    __shared__ int  scnt[2];
    __shared__ int  swsum[8];

    int tid  = threadIdx.x;
    int lane = tid & 31, w = tid >> 5;
    int half = w >> 2;
    int wh   = w & 3;
    int th   = tid & 127;
    int i    = blockIdx.x * 2 + half;

    sri[half][th] = g_bits[i * NW + th];
    __syncthreads();

    unsigned word = sri[half][th];
    int c = __popc(word);
    int x = c;
    #pragma unroll
    for (int o = 1; o < 32; o <<= 1) {
        int y = __shfl_up_sync(0xffffffffu, x, o);
        if (lane >= o) x += y;
    }
    if (lane == 31) warpsum[w] = x;
    __syncthreads();
    if (tid < 2) {
        int s = 0;
        #pragma unroll
        for (int k = 0; k < 4; k++) {
            int t = warpsum[tid * 4 + k];
            warpbase[tid * 4 + k] = s;
            s += t;
        }
        scnt[tid] = s;
    }
    __syncthreads();
    {
        int base = warpbase[w] + x - c;
        unsigned ww = word;
        while (ww) {
            int bit = __ffs(ww) - 1;
            ww &= ww - 1;
            list[half][base++] = th * 32 + bit;
        }
    }
    __syncthreads();

    int cnt = scnt[half];
    int cpw = (cnt + 3) >> 2;
    int start = wh * cpw;
    int end   = min(cnt, start + cpw);

    uint4 ri = ((const uint4*)&sri[half][0])[lane];
    const uint4 zz = make_uint4(0u, 0u, 0u, 0u);
    int my = 0;
    for (int p0 = start; p0 < end; p0 += 8) {
        uint4 x0 = zz, x1 = zz, x2 = zz, x3 = zz,
              x4 = zz, x5 = zz, x6 = zz, x7 = zz;
        if (p0 + 0 < end) x0 = ((const uint4*)&g_bits[list[half][p0 + 0] * NW])[lane];
        if (p0 + 1 < end) x1 = ((const uint4*)&g_bits[list[half][p0 + 1] * NW])[lane];
        if (p0 + 2 < end) x2 = ((const uint4*)&g_bits[list[half][p0 + 2] * NW])[lane];
        if (p0 + 3 < end) x3 = ((const uint4*)&g_bits[list[half][p0 + 3] * NW])[lane];
        if (p0 + 4 < end) x4 = ((const uint4*)&g_bits[list[half][p0 + 4] * NW])[lane];
        if (p0 + 5 < end) x5 = ((const uint4*)&g_bits[list[half][p0 + 5] * NW])[lane];
        if (p0 + 6 < end) x6 = ((const uint4*)&g_bits[list[half][p0 + 6] * NW])[lane];
        if (p0 + 7 < end) x7 = ((const uint4*)&g_bits[list[half][p0 + 7] * NW])[lane];
        my += __popc(x0.x & ri.x) + __popc(x0.y & ri.y)
            + __popc(x0.z & ri.z) + __popc(x0.w & ri.w);
        my += __popc(x1.x & ri.x) + __popc(x1.y & ri.y)
            + __popc(x1.z & ri.z) + __popc(x1.w & ri.w);
        my += __popc(x2.x & ri.x) + __popc(x2.y & ri.y)
            + __popc(x2.z & ri.z) + __popc(x2.w & ri.w);
        my += __popc(x3.x & ri.x) + __popc(x3.y & ri.y)
            + __popc(x3.z & ri.z) + __popc(x3.w & ri.w);
        my += __popc(x4.x & ri.x) + __popc(x4.y & ri.y)
            + __popc(x4.z & ri.z) + __popc(x4.w & ri.w);
        my += __popc(x5.x & ri.x) + __popc(x5.y & ri.y)
            + __popc(x5.z & ri.z) + __popc(x5.w & ri.w);
        my += __popc(x6.x & ri.x) + __popc(x6.y & ri.y)
            + __popc(x6.z & ri.z) + __popc(x6.w & ri.w);
        my += __popc(x7.x & ri.x) + __popc(x7.y & ri.y)
            + __popc(x7.z & ri.z) + __popc(x7.w & ri.w);
    }
    #pragma unroll
    for (int o = 16; o; o >>= 1) my += __shfl_down_sync(0xffffffffu, my, o);
    if (lane == 0) swsum[w] = my;
    __syncthreads();
    if ((tid & 127) == 0) {
        int h = tid >> 7;
        int tot = swsum[h * 4 + 0] + swsum[h * 4 + 1]
                + swsum[h * 4 + 2] + swsum[h * 4 + 3];
        g_C[blockIdx.x * 2 + h] = (float)tot * g_invden[blockIdx.x * 2 + h];
    }
}

// =======================================================================
// K2b: proj | egemm striped 1:1; outputs stored as bf16
// =======================================================================
__global__ void __launch_bounds__(256)
k_pe(const float* __restrict__ emb,
     const float* __restrict__ Wp,
     const int*   __restrict__ ntype,
     const float* __restrict__ Wb,
     const float* __restrict__ bb) {
    __shared__ __align__(16) char sm[33 * 1024];    // union
    __shared__ int sty[16];

    int b   = blockIdx.x;
    int tid = threadIdx.x;
    int r   = b & 1, q = b >> 1;

    if (r == 0) {
        float* semb = (float*)sm;
        float* sred = (float*)(sm + 10 * 1024 + 256);
        int n0 = q * 16;
        int e  = tid & 127, g = tid >> 7;
        for (int idx = tid; idx < 16 * DD; idx += 256) {
            int d = idx & 127, n = idx >> 7;
            semb[d * 20 + n] = emb[(n0 + n) * DD + d];
        }
        if (tid < 16) sty[tid] = ntype[n0 + tid];
        __syncthreads();
        int ty[16];
        #pragma unroll
        for (int n = 0; n < 16; n++) ty[n] = sty[n];
        float acc[16];
        #pragma unroll
        for (int n = 0; n < 16; n++) acc[n] = 0.f;
        int dbase = g * 64;
        for (int i = 0; i < 64; i += 2) {
            int da = dbase + i, db = dbase + i + 1;
            float w0a = Wp[(0 * DD + da) * DD + e];
            float w1a = Wp[(1 * DD + da) * DD + e];
            float w2a = Wp[(2 * DD + da) * DD + e];
            float w0b = Wp[(0 * DD + db) * DD + e];
            float w1b = Wp[(1 * DD + db) * DD + e];
            float w2b = Wp[(2 * DD + db) * DD + e];
            const float4* rowa = (const float4*)&semb[da * 20];
            const float4* rowb = (const float4*)&semb[db * 20];
            #pragma unroll
            for (int p = 0; p < 4; p++) {
                float4 va = rowa[p];
                { int n=4*p+0; float wv=(ty[n]==0)?w0a:((ty[n]==1)?w1a:w2a); acc[n]+=va.x*wv; }
                { int n=4*p+1; float wv=(ty[n]==0)?w0a:((ty[n]==1)?w1a:w2a); acc[n]+=va.y*wv; }
                { int n=4*p+2; float wv=(ty[n]==0)?w0a:((ty[n]==1)?w1a:w2a); acc[n]+=va.z*wv; }
                { int n=4*p+3; float wv=(ty[n]==0)?w0a:((ty[n]==1)?w1a:w2a); acc[n]+=va.w*wv; }
            }
            #pragma unroll
            for (int p = 0; p < 4; p++) {
                float4 vb = rowb[p];
                { int n=4*p+0; float wv=(ty[n]==0)?w0b:((ty[n]==1)?w1b:w2b); acc[n]+=vb.x*wv; }
                { int n=4*p+1; float wv=(ty[n]==0)?w0b:((ty[n]==1)?w1b:w2b); acc[n]+=vb.y*wv; }
                { int n=4*p+2; float wv=(ty[n]==0)?w0b:((ty[n]==1)?w1b:w2b); acc[n]+=vb.z*wv; }
                { int n=4*p+3; float wv=(ty[n]==0)?w0b:((ty[n]==1)?w1b:w2b); acc[n]+=vb.w*wv; }
            }
        }
        if (g == 1) {
            #pragma unroll
            for (int n = 0; n < 16; n++) sred[n * DD + e] = acc[n];
        }
        __syncthreads();
        if (g == 0) {
            #pragma unroll
            for (int n = 0; n < 16; n++)
                g_projh[(n0 + n) * DD + e] =
                    __float2bfloat16(acc[n] + sred[n * DD + e]);
        }
    } else {
        float* sbuf = (float*)sm;
        int n0 = q * 16;
        int e  = tid & 127, g = tid >> 7;
        for (int idx = tid; idx < 16 * 512; idx += 256) {
            int n = idx >> 9, rd = idx & 511;
            sbuf[rd * 16 + n] = g_hbar[(n0 + n) * 512 + rd];
        }
        __syncthreads();
        unsigned long long acc[8];
        #pragma unroll
        for (int p = 0; p < 8; p++) acc[p] = 0ull;
        int rdbase = g * 256;
        for (int i2 = 0; i2 < 256; i2 += 8) {
            float wv[8];
            #pragma unroll
            for (int t = 0; t < 8; t++)
                wv[t] = Wb[(rdbase + i2 + t) * DD + e];
            #pragma unroll
            for (int t = 0; t < 8; t++) {
                unsigned long long w2 = pk(wv[t], wv[t]);
                const ulonglong2* row =
                    (const ulonglong2*)&sbuf[(rdbase + i2 + t) * 16];
                ulonglong2 v0 = row[0];
                ulonglong2 v1 = row[1];
                ffma2(acc[0], v0.x, w2);
                ffma2(acc[1], v0.y, w2);
                ffma2(acc[2], v1.x, w2);
                ffma2(acc[3], v1.y, w2);
                ulonglong2 v2 = row[2];
                ulonglong2 v3 = row[3];
                ffma2(acc[4], v2.x, w2);
                ffma2(acc[5], v2.y, w2);
                ffma2(acc[6], v3.x, w2);
                ffma2(acc[7], v3.y, w2);
            }
        }
        float a[16];
        #pragma unroll
        for (int p = 0; p < 8; p++) upk(a[2 * p], a[2 * p + 1], acc[p]);
        __syncthreads();
        if (g == 1) {
            #pragma unroll
            for (int n = 0; n < 16; n++) sbuf[n * DD + e] = a[n];
        }
        __syncthreads();
        if (g == 0) {
            float bsum = bb[e] + bb[DD + e] + bb[2 * DD + e] + bb[3 * DD + e];
            #pragma unroll
            for (int n = 0; n < 16; n++) {
                float t = a[n] + sbuf[n * DD + e];
                float h = (t + bsum) * 0.25f;
                g_epsh[(n0 + n) * DD + e] =
                    __float2bfloat16(1.0f / (1.0f + expf(-h)));
            }
        }
    }
}

// =======================================================================
// K3: per-pair score (warp per pair), bf16 vectors (8B/lane)
// =======================================================================
__global__ void __launch_bounds__(256)
k_pairs(const int*   __restrict__ pairs,
        const float* __restrict__ q1p,
        const float* __restrict__ q2p,
        float*       __restrict__ out) {
    int gw   = (blockIdx.x * blockDim.x + threadIdx.x) >> 5;
    int lane = threadIdx.x & 31;
    if (gw >= PP) return;
    int pm = pairs[gw * 2 + 0];
    int pn = pairs[gw * 2 + 1];

    // front-batch independent loads
    uint2 ap = __ldg(&((const uint2*)&g_projh[pm * DD])[lane]);
    uint2 bp = __ldg(&((const uint2*)&g_projh[pn * DD])[lane]);
    uint2 am = __ldg(&((const uint2*)&g_embh [pm * DD])[lane]);
    uint2 bm2= __ldg(&((const uint2*)&g_embh [pn * DD])[lane]);
    uint2 ae = __ldg(&((const uint2*)&g_epsh [pm * DD])[lane]);
    uint2 be = __ldg(&((const uint2*)&g_epsh [pn * DD])[lane]);
    uint4 wm = ((const uint4*)&g_bits[pm * NW])[lane];
    uint4 wn = ((const uint4*)&g_bits[pn * NW])[lane];

    float2 a0 = bcvt(ap.x), a1 = bcvt(ap.y);
    float2 b0 = bcvt(bp.x), b1 = bcvt(bp.y);
    float d0 = a0.x - b0.x, d1 = a0.y - b0.y, d2 = a1.x - b1.x, d3 = a1.y - b1.y;
    float s1 = d0*d0 + d1*d1 + d2*d2 + d3*d3;

    float2 m0 = bcvt(am.x), m1 = bcvt(am.y);
    float2 n0 = bcvt(bm2.x), n1 = bcvt(bm2.y);
    float e0 = m0.x - n0.x, e1 = m0.y - n0.y, e2 = m1.x - n1.x, e3 = m1.y - n1.y;
    float s2 = e0*e0 + e1*e1 + e2*e2 + e3*e3;

    float2 p0 = bcvt(ae.x), p1 = bcvt(ae.y);
    float2 r0 = bcvt(be.x), r1 = bcvt(be.y);
    float s3 = p0.x*r0.x + p0.y*r0.y + p1.x*r1.x + p1.y*r1.y;

    float cs = 0.f;
    {
        unsigned ws[4] = { wm.x & wn.x, wm.y & wn.y, wm.z & wn.z, wm.w & wn.w };
        #pragma unroll
        for (int c = 0; c < 4; c++) {
            unsigned word = ws[c];
            int j0 = (lane * 4 + c) * 32;
            while (word) {
                int bpos = __ffs(word) - 1;
                word &= word - 1;
                cs += g_C[j0 + bpos];
            }
        }
    }

    #pragma unroll
    for (int o = 16; o; o >>= 1) {
        s1 += __shfl_xor_sync(0xffffffffu, s1, o);
        s2 += __shfl_xor_sync(0xffffffffu, s2, o);
        s3 += __shfl_xor_sync(0xffffffffu, s3, o);
        cs += __shfl_xor_sync(0xffffffffu, cs, o);
    }

    if (lane == 0) {
        float gamma = -sqrtf(s1);
        float g     = -s2;
        float lamb  = gamma + g_alpha + cs * g + s3 * (1.0f / (float)DD);
        float lam   = expf(lamb);
        float z     = q1p[0] * lam + q2p[0];
        out[gw] = 1.0f / (1.0f + expf(-z));
    }
}

// ---------------- launcher ----------------
extern "C" void kernel_launch(void* const* d_in, const int* in_sizes, int n_in,
                              void* d_out, int out_size) {
    const int*   pairs   = (const int*)  d_in[0];
    const int*   adj     = (const int*)  d_in[1];
    const int*   nidx    = (const int*)  d_in[2];
    const int*   ntype   = (const int*)  d_in[3];
    const float* tev     = (const float*)d_in[4];
    const float* emb     = (const float*)d_in[5];
    const float* Wp      = (const float*)d_in[6];
    const float* Wb      = (const float*)d_in[7];
    const float* bb      = (const float*)d_in[8];
    const float* theta_p = (const float*)d_in[9];
    const float* q1p     = (const float*)d_in[10];
    const float* q2p     = (const float*)d_in[11];
    float*       out     = (float*)d_out;

    k_0    <<<256, 256>>>(emb);
    k_1    <<<GRID_1, 256>>>(adj, nidx, tev, theta_p);
    k_tri  <<<NN / 2, 256>>>();
    k_pe   <<<512, 256>>>(emb, Wp, ntype, Wb, bb);
    k_pairs<<<PP / 8, 256>>>(pairs, q1p, q2p, out);
}

// round 15
// speedup vs baseline: 1.0623x; 1.0623x over previous
#include <cuda_runtime.h>
#include <cuda_bf16.h>
#include <cstdint>

// Problem constants
#define NN   4096
#define PP   32768
#define EE   4096
#define DD   128
#define RR   4
#define KK   16
#define NW   128       // 4096 bits / 32 words per adjacency row

// ---- K1 striping: group of 3 = 2 pack rows + 1 gather block; +1 tail ----
#define GRID_1  (2048 * 3 + 1)

// ---------------- device scratch ----------------
__device__ unsigned       g_bits  [NN * NW];
__device__ float          g_C     [NN];
__device__ float          g_invden[NN];
__device__ __nv_bfloat16  g_embh  [NN * DD];      // bf16 copy of emb
__device__ __nv_bfloat16  g_projh [NN * DD];      // bf16 proj
__device__ __nv_bfloat16  g_epsh  [NN * DD];      // bf16 eps
__device__ float          g_hbar  [NN * RR * DD]; // fp32 h_bar
__device__ float          g_alpha;

// ---------------- helpers ----------------
__device__ __forceinline__ float2 bcvt(unsigned u) {
    __nv_bfloat162 h = *reinterpret_cast<__nv_bfloat162*>(&u);
    return __bfloat1622float2(h);
}
__device__ __forceinline__ unsigned f2tf(float x) {
    unsigned r;
    asm("cvt.rna.tf32.f32 %0, %1;" : "=r"(r) : "f"(x));
    return r;
}
// mma.m16n8k8 tf32: D += A*B  (fp32 accum in place)
__device__ __forceinline__ void mma8(float* c,
                                     unsigned a0, unsigned a1,
                                     unsigned a2, unsigned a3,
                                     unsigned b0, unsigned b1) {
    asm volatile(
        "mma.sync.aligned.m16n8k8.row.col.f32.tf32.tf32.f32 "
        "{%0,%1,%2,%3}, {%4,%5,%6,%7}, {%8,%9}, {%0,%1,%2,%3};"
        : "+f"(c[0]), "+f"(c[1]), "+f"(c[2]), "+f"(c[3])
        : "r"(a0), "r"(a1), "r"(a2), "r"(a3), "r"(b0), "r"(b1));
}

// =======================================================================
// K0: emb (fp32) -> g_embh (bf16)
// =======================================================================
__global__ void __launch_bounds__(256)
k_0(const float* __restrict__ emb) {
    int t = blockIdx.x * 256 + threadIdx.x;
    const float4* src = (const float4*)emb;
    float4 a = src[t * 2];
    float4 b = src[t * 2 + 1];
    __nv_bfloat162* dst = (__nv_bfloat162*)g_embh;
    dst[t * 4 + 0] = __floats2bfloat162_rn(a.x, a.y);
    dst[t * 4 + 1] = __floats2bfloat162_rn(a.z, a.w);
    dst[t * 4 + 2] = __floats2bfloat162_rn(b.x, b.y);
    dst[t * 4 + 3] = __floats2bfloat162_rn(b.z, b.w);
}

// =======================================================================
// K1: pack | gather(bf16 emb) | alpha, striped  [unchanged R14]
// =======================================================================
__global__ void __launch_bounds__(256)
k_1(const int*   __restrict__ adj,
    const int*   __restrict__ nidx,
    const float* __restrict__ tev,
    const float* __restrict__ theta_p) {
    __shared__ int   sdeg[8];
    __shared__ float sw[8];

    int b    = blockIdx.x;
    int tid  = threadIdx.x;
    int lane = tid & 31, w = tid >> 5;

    if (b < 2048 * 3) {
        int r = b % 3, q = b / 3;
        if (r < 2) {
            int row = q * 2 + r;
            const int* a = adj + (size_t)row * NN;
            int v[16];
            #pragma unroll
            for (int i = 0; i < 16; i++)
                v[i] = a[(w * 16 + i) * 32 + lane];
            unsigned keep = 0;
            #pragma unroll
            for (int i = 0; i < 16; i++) {
                unsigned m = __ballot_sync(0xffffffffu, v[i] != 0);
                if (lane == i) keep = m;
            }
            if (lane < 16)
                g_bits[row * NW + w * 16 + lane] = keep;
            int dsum = (lane < 16) ? __popc(keep) : 0;
            #pragma unroll
            for (int o = 16; o; o >>= 1)
                dsum += __shfl_down_sync(0xffffffffu, dsum, o);
            if (lane == 0) sdeg[w] = dsum;
            __syncthreads();
            if (tid == 0) {
                int s = 0;
                #pragma unroll
                for (int i = 0; i < 8; i++) s += sdeg[i];
                float d   = (float)s;
                float den = d * (d - 1.0f);
                if (den == 0.0f) den = 1e-6f;
                g_invden[row] = 2.0f / den;
            }
        } else {
            int unit = q * 8 + w;
            const uint2* e2 = (const uint2*)g_embh;
            int nid = 0;
            if (lane < KK) nid = nidx[unit * KK + lane];
            float4 acc = make_float4(0.f, 0.f, 0.f, 0.f);
            #pragma unroll
            for (int k = 0; k < KK; k++) {
                int id = __shfl_sync(0xffffffffu, nid, k);
                uint2 v = __ldg(&e2[id * 32 + lane]);
                float2 lo = bcvt(v.x), hi = bcvt(v.y);
                acc.x += lo.x; acc.y += lo.y; acc.z += hi.x; acc.w += hi.y;
            }
            ((float4*)g_hbar)[unit * 32 + lane] =
                make_float4(acc.x * 0.0625f, acc.y * 0.0625f,
                            acc.z * 0.0625f, acc.w * 0.0625f);
        }
    } else {
        float th = theta_p[0];
        float s  = 0.f;
        for (int i = tid; i < EE; i += 256)
            s += expf(-th * (1.0f - tev[i]));
        #pragma unroll
        for (int o = 16; o; o >>= 1) s += __shfl_down_sync(0xffffffffu, s, o);
        if (lane == 0) sw[w] = s;
        __syncthreads();
        if (tid == 0) {
            float tot = 0.f;
            #pragma unroll
            for (int i = 0; i < 8; i++) tot += sw[i];
            g_alpha = tot;
        }
    }
}

// =======================================================================
// K2: tri — 2 rows/block, MLP-8 chunks  [unchanged R14]
// =======================================================================
__global__ void __launch_bounds__(256)
k_tri() {
    __shared__ __align__(16) unsigned sri[2][NW];
    __shared__ int  list[2][192];
    __shared__ int  warpsum[8], warpbase[8];
    __shared__ int  scnt[2];
    __shared__ int  swsum[8];

    int tid  = threadIdx.x;
    int lane = tid & 31, w = tid >> 5;
    int half = w >> 2;
    int wh   = w & 3;
    int th   = tid & 127;
    int i    = blockIdx.x * 2 + half;

    sri[half][th] = g_bits[i * NW + th];
    __syncthreads();

    unsigned word = sri[half][th];
    int c = __popc(word);
    int x = c;
    #pragma unroll
    for (int o = 1; o < 32; o <<= 1) {
        int y = __shfl_up_sync(0xffffffffu, x, o);
        if (lane >= o) x += y;
    }
    if (lane == 31) warpsum[w] = x;
    __syncthreads();
    if (tid < 2) {
        int s = 0;
        #pragma unroll
        for (int k = 0; k < 4; k++) {
            int t = warpsum[tid * 4 + k];
            warpbase[tid * 4 + k] = s;
            s += t;
        }
        scnt[tid] = s;
    }
    __syncthreads();
    {
        int base = warpbase[w] + x - c;
        unsigned ww = word;
        while (ww) {
            int bit = __ffs(ww) - 1;
            ww &= ww - 1;
            list[half][base++] = th * 32 + bit;
        }
    }
    __syncthreads();

    int cnt = scnt[half];
    int cpw = (cnt + 3) >> 2;
    int start = wh * cpw;
    int end   = min(cnt, start + cpw);

    uint4 ri = ((const uint4*)&sri[half][0])[lane];
    const uint4 zz = make_uint4(0u, 0u, 0u, 0u);
    int my = 0;
    for (int p0 = start; p0 < end; p0 += 8) {
        uint4 x0 = zz, x1 = zz, x2 = zz, x3 = zz,
              x4 = zz, x5 = zz, x6 = zz, x7 = zz;
        if (p0 + 0 < end) x0 = ((const uint4*)&g_bits[list[half][p0 + 0] * NW])[lane];
        if (p0 + 1 < end) x1 = ((const uint4*)&g_bits[list[half][p0 + 1] * NW])[lane];
        if (p0 + 2 < end) x2 = ((const uint4*)&g_bits[list[half][p0 + 2] * NW])[lane];
        if (p0 + 3 < end) x3 = ((const uint4*)&g_bits[list[half][p0 + 3] * NW])[lane];
        if (p0 + 4 < end) x4 = ((const uint4*)&g_bits[list[half][p0 + 4] * NW])[lane];
        if (p0 + 5 < end) x5 = ((const uint4*)&g_bits[list[half][p0 + 5] * NW])[lane];
        if (p0 + 6 < end) x6 = ((const uint4*)&g_bits[list[half][p0 + 6] * NW])[lane];
        if (p0 + 7 < end) x7 = ((const uint4*)&g_bits[list[half][p0 + 7] * NW])[lane];
        my += __popc(x0.x & ri.x) + __popc(x0.y & ri.y)
            + __popc(x0.z & ri.z) + __popc(x0.w & ri.w);
        my += __popc(x1.x & ri.x) + __popc(x1.y & ri.y)
            + __popc(x1.z & ri.z) + __popc(x1.w & ri.w);
        my += __popc(x2.x & ri.x) + __popc(x2.y & ri.y)
            + __popc(x2.z & ri.z) + __popc(x2.w & ri.w);
        my += __popc(x3.x & ri.x) + __popc(x3.y & ri.y)
            + __popc(x3.z & ri.z) + __popc(x3.w & ri.w);
        my += __popc(x4.x & ri.x) + __popc(x4.y & ri.y)
            + __popc(x4.z & ri.z) + __popc(x4.w & ri.w);
        my += __popc(x5.x & ri.x) + __popc(x5.y & ri.y)
            + __popc(x5.z & ri.z) + __popc(x5.w & ri.w);
        my += __popc(x6.x & ri.x) + __popc(x6.y & ri.y)
            + __popc(x6.z & ri.z) + __popc(x6.w & ri.w);
        my += __popc(x7.x & ri.x) + __popc(x7.y & ri.y)
            + __popc(x7.z & ri.z) + __popc(x7.w & ri.w);
    }
    #pragma unroll
    for (int o = 16; o; o >>= 1) my += __shfl_down_sync(0xffffffffu, my, o);
    if (lane == 0) swsum[w] = my;
    __syncthreads();
    if ((tid & 127) == 0) {
        int h = tid >> 7;
        int tot = swsum[h * 4 + 0] + swsum[h * 4 + 1]
                + swsum[h * 4 + 2] + swsum[h * 4 + 3];
        g_C[blockIdx.x * 2 + h] = (float)tot * g_invden[blockIdx.x * 2 + h];
    }
}

// =======================================================================
// K3: egemm via tf32 mma — eps = sigmoid((hbar @ Wb + sum_r b)/4)
//     16 nodes/block, 128 threads (4 warps x 32 e-cols)
// =======================================================================
__global__ void __launch_bounds__(128)
k_egemm(const float* __restrict__ Wb,
        const float* __restrict__ bb) {
    __shared__ float sA[16 * 516];           // 33 KB, stride 516 (conflict-free)
    int tid  = threadIdx.x;
    int lane = tid & 31, w = tid >> 5;       // w in 0..3
    int g    = lane >> 2, tig = lane & 3;
    int n0   = blockIdx.x * 16;

    // stage A = hbar tile [16 x 512], tf32-rounded
    for (int idx = tid; idx < 16 * 512; idx += 128) {
        int n = idx >> 9, k = idx & 511;
        sA[n * 516 + k] = __uint_as_float(f2tf(g_hbar[(n0 + n) * 512 + k]));
    }
    __syncthreads();

    float acc[4][4];
    #pragma unroll
    for (int ct = 0; ct < 4; ct++)
        #pragma unroll
        for (int q = 0; q < 4; q++) acc[ct][q] = 0.f;

    const unsigned* uA = (const unsigned*)sA;
    #pragma unroll 4
    for (int ks = 0; ks < 64; ks++) {
        int k0 = ks * 8;
        unsigned a0 = uA[g * 516 + k0 + tig];
        unsigned a1 = uA[(g + 8) * 516 + k0 + tig];
        unsigned a2 = uA[g * 516 + k0 + tig + 4];
        unsigned a3 = uA[(g + 8) * 516 + k0 + tig + 4];
        #pragma unroll
        for (int ct = 0; ct < 4; ct++) {
            int col = w * 32 + ct * 8 + g;
            unsigned b0 = f2tf(__ldg(&Wb[(k0 + tig) * DD + col]));
            unsigned b1 = f2tf(__ldg(&Wb[(k0 + tig + 4) * DD + col]));
            mma8(acc[ct], a0, a1, a2, a3, b0, b1);
        }
    }

    // epilogue: + bias sum, /4, sigmoid, store bf16
    #pragma unroll
    for (int ct = 0; ct < 4; ct++) {
        int e0 = w * 32 + ct * 8 + 2 * tig;
        int e1 = e0 + 1;
        float bs0 = bb[e0] + bb[DD + e0] + bb[2 * DD + e0] + bb[3 * DD + e0];
        float bs1 = bb[e1] + bb[DD + e1] + bb[2 * DD + e1] + bb[3 * DD + e1];
        float h00 = (acc[ct][0] + bs0) * 0.25f;
        float h01 = (acc[ct][1] + bs1) * 0.25f;
        float h10 = (acc[ct][2] + bs0) * 0.25f;
        float h11 = (acc[ct][3] + bs1) * 0.25f;
        g_epsh[(n0 + g) * DD + e0]     = __float2bfloat16(1.0f / (1.0f + expf(-h00)));
        g_epsh[(n0 + g) * DD + e1]     = __float2bfloat16(1.0f / (1.0f + expf(-h01)));
        g_epsh[(n0 + g + 8) * DD + e0] = __float2bfloat16(1.0f / (1.0f + expf(-h10)));
        g_epsh[(n0 + g + 8) * DD + e1] = __float2bfloat16(1.0f / (1.0f + expf(-h11)));
    }
}

// =======================================================================
// K4: proj via tf32 mma — 3 type-GEMMs, select at epilogue
//     16 nodes/block, 128 threads (4 warps x 32 e-cols)
// =======================================================================
__global__ void __launch_bounds__(128)
k_proj(const float* __restrict__ emb,
       const float* __restrict__ Wp,
       const int*   __restrict__ ntype) {
    __shared__ float sA[16 * 132];           // 8.4 KB, stride 132 (conflict-free)
    __shared__ int   sty[16];
    int tid  = threadIdx.x;
    int lane = tid & 31, w = tid >> 5;
    int g    = lane >> 2, tig = lane & 3;
    int n0   = blockIdx.x * 16;

    for (int idx = tid; idx < 16 * DD; idx += 128) {
        int n = idx >> 7, d = idx & 127;
        sA[n * 132 + d] = __uint_as_float(f2tf(emb[(n0 + n) * DD + d]));
    }
    if (tid < 16) sty[tid] = ntype[n0 + tid];
    __syncthreads();

    float acc[3][4][4];
    #pragma unroll
    for (int t = 0; t < 3; t++)
        #pragma unroll
        for (int ct = 0; ct < 4; ct++)
            #pragma unroll
            for (int q = 0; q < 4; q++) acc[t][ct][q] = 0.f;

    const unsigned* uA = (const unsigned*)sA;
    #pragma unroll 2
    for (int ks = 0; ks < 16; ks++) {
        int k0 = ks * 8;
        unsigned a0 = uA[g * 132 + k0 + tig];
        unsigned a1 = uA[(g + 8) * 132 + k0 + tig];
        unsigned a2 = uA[g * 132 + k0 + tig + 4];
        unsigned a3 = uA[(g + 8) * 132 + k0 + tig + 4];
        #pragma unroll
        for (int t = 0; t < 3; t++) {
            const float* W = Wp + t * DD * DD;
            #pragma unroll
            for (int ct = 0; ct < 4; ct++) {
                int col = w * 32 + ct * 8 + g;
                unsigned b0 = f2tf(__ldg(&W[(k0 + tig) * DD + col]));
                unsigned b1 = f2tf(__ldg(&W[(k0 + tig + 4) * DD + col]));
                mma8(acc[t][ct], a0, a1, a2, a3, b0, b1);
            }
        }
    }

    int ty0 = sty[g], ty1 = sty[g + 8];
    #pragma unroll
    for (int ct = 0; ct < 4; ct++) {
        int e0 = w * 32 + ct * 8 + 2 * tig;
        int e1 = e0 + 1;
        float v00 = (ty0 == 0) ? acc[0][ct][0] : ((ty0 == 1) ? acc[1][ct][0] : acc[2][ct][0]);
        float v01 = (ty0 == 0) ? acc[0][ct][1] : ((ty0 == 1) ? acc[1][ct][1] : acc[2][ct][1]);
        float v10 = (ty1 == 0) ? acc[0][ct][2] : ((ty1 == 1) ? acc[1][ct][2] : acc[2][ct][2]);
        float v11 = (ty1 == 0) ? acc[0][ct][3] : ((ty1 == 1) ? acc[1][ct][3] : acc[2][ct][3]);
        g_projh[(n0 + g) * DD + e0]     = __float2bfloat16(v00);
        g_projh[(n0 + g) * DD + e1]     = __float2bfloat16(v01);
        g_projh[(n0 + g + 8) * DD + e0] = __float2bfloat16(v10);
        g_projh[(n0 + g + 8) * DD + e1] = __float2bfloat16(v11);
    }
}

// =======================================================================
// K5: per-pair score (warp per pair), bf16 vectors  [unchanged R14]
// =======================================================================
__global__ void __launch_bounds__(256)
k_pairs(const int*   __restrict__ pairs,
        const float* __restrict__ q1p,
        const float* __restrict__ q2p,
        float*       __restrict__ out) {
    int gw   = (blockIdx.x * blockDim.x + threadIdx.x) >> 5;
    int lane = threadIdx.x & 31;
    if (gw >= PP) return;
    int pm = pairs[gw * 2 + 0];
    int pn = pairs[gw * 2 + 1];

    uint2 ap = __ldg(&((const uint2*)&g_projh[pm * DD])[lane]);
    uint2 bp = __ldg(&((const uint2*)&g_projh[pn * DD])[lane]);
    uint2 am = __ldg(&((const uint2*)&g_embh [pm * DD])[lane]);
    uint2 bm2= __ldg(&((const uint2*)&g_embh [pn * DD])[lane]);
    uint2 ae = __ldg(&((const uint2*)&g_epsh [pm * DD])[lane]);
    uint2 be = __ldg(&((const uint2*)&g_epsh [pn * DD])[lane]);
    uint4 wm = ((const uint4*)&g_bits[pm * NW])[lane];
    uint4 wn = ((const uint4*)&g_bits[pn * NW])[lane];

    float2 a0 = bcvt(ap.x), a1 = bcvt(ap.y);
    float2 b0 = bcvt(bp.x), b1 = bcvt(bp.y);
    float d0 = a0.x - b0.x, d1 = a0.y - b0.y, d2 = a1.x - b1.x, d3 = a1.y - b1.y;
    float s1 = d0*d0 + d1*d1 + d2*d2 + d3*d3;

    float2 m0 = bcvt(am.x), m1 = bcvt(am.y);
    float2 n0 = bcvt(bm2.x), n1 = bcvt(bm2.y);
    float e0 = m0.x - n0.x, e1 = m0.y - n0.y, e2 = m1.x - n1.x, e3 = m1.y - n1.y;
    float s2 = e0*e0 + e1*e1 + e2*e2 + e3*e3;

    float2 p0 = bcvt(ae.x), p1 = bcvt(ae.y);
    float2 r0 = bcvt(be.x), r1 = bcvt(be.y);
    float s3 = p0.x*r0.x + p0.y*r0.y + p1.x*r1.x + p1.y*r1.y;

    float cs = 0.f;
    {
        unsigned ws[4] = { wm.x & wn.x, wm.y & wn.y, wm.z & wn.z, wm.w & wn.w };
        #pragma unroll
        for (int c = 0; c < 4; c++) {
            unsigned word = ws[c];
            int j0 = (lane * 4 + c) * 32;
            while (word) {
                int bpos = __ffs(word) - 1;
                word &= word - 1;
                cs += g_C[j0 + bpos];
            }
        }
    }

    #pragma unroll
    for (int o = 16; o; o >>= 1) {
        s1 += __shfl_xor_sync(0xffffffffu, s1, o);
        s2 += __shfl_xor_sync(0xffffffffu, s2, o);
        s3 += __shfl_xor_sync(0xffffffffu, s3, o);
        cs += __shfl_xor_sync(0xffffffffu, cs, o);
    }

    if (lane == 0) {
        float gamma = -sqrtf(s1);
        float g     = -s2;
        float lamb  = gamma + g_alpha + cs * g + s3 * (1.0f / (float)DD);
        float lam   = expf(lamb);
        float z     = q1p[0] * lam + q2p[0];
        out[gw] = 1.0f / (1.0f + expf(-z));
    }
}

// ---------------- launcher ----------------
extern "C" void kernel_launch(void* const* d_in, const int* in_sizes, int n_in,
                              void* d_out, int out_size) {
    const int*   pairs   = (const int*)  d_in[0];
    const int*   adj     = (const int*)  d_in[1];
    const int*   nidx    = (const int*)  d_in[2];
    const int*   ntype   = (const int*)  d_in[3];
    const float* tev     = (const float*)d_in[4];
    const float* emb     = (const float*)d_in[5];
    const float* Wp      = (const float*)d_in[6];
    const float* Wb      = (const float*)d_in[7];
    const float* bb      = (const float*)d_in[8];
    const float* theta_p = (const float*)d_in[9];
    const float* q1p     = (const float*)d_in[10];
    const float* q2p     = (const float*)d_in[11];
    float*       out     = (float*)d_out;

    k_0    <<<256, 256>>>(emb);
    k_1    <<<GRID_1, 256>>>(adj, nidx, tev, theta_p);
    k_tri  <<<NN / 2, 256>>>();
    k_proj <<<NN / 16, 128>>>(emb, Wp, ntype);
    k_egemm<<<NN / 16, 128>>>(Wb, bb);
    k_pairs<<<PP / 8, 256>>>(pairs, q1p, q2p, out);
}

// round 16
// speedup vs baseline: 1.1317x; 1.0653x over previous
#include <cuda_runtime.h>
#include <cuda_bf16.h>
#include <cstdint>

// Problem constants
#define NN   4096
#define PP   32768
#define EE   4096
#define DD   128
#define RR   4
#define KK   16
#define NW   128       // 4096 bits / 32 words per adjacency row

// ---- K1 striping: group of 3 = 2 pack rows + 1 gather block; +1 tail ----
#define GRID_1  (2048 * 3 + 1)

// ---------------- device scratch ----------------
__device__ unsigned       g_bits  [NN * NW];
__device__ float          g_C     [NN];
__device__ float          g_invden[NN];
__device__ __nv_bfloat16  g_embh  [NN * DD];      // bf16 copy of emb
__device__ __nv_bfloat16  g_projh [NN * DD];      // bf16 proj
__device__ __nv_bfloat16  g_epsh  [NN * DD];      // bf16 eps
__device__ float          g_hbar  [NN * RR * DD]; // fp32 h_bar
__device__ float          g_alpha;

// ---------------- helpers ----------------
__device__ __forceinline__ float2 bcvt(unsigned u) {
    __nv_bfloat162 h = *reinterpret_cast<__nv_bfloat162*>(&u);
    return __bfloat1622float2(h);
}
__device__ __forceinline__ unsigned f2tf(float x) {
    unsigned r;
    asm("cvt.rna.tf32.f32 %0, %1;" : "=r"(r) : "f"(x));
    return r;
}
// mma.m16n8k8 tf32: D += A*B  (fp32 accum in place)
__device__ __forceinline__ void mma8(float* c,
                                     unsigned a0, unsigned a1,
                                     unsigned a2, unsigned a3,
                                     unsigned b0, unsigned b1) {
    asm volatile(
        "mma.sync.aligned.m16n8k8.row.col.f32.tf32.tf32.f32 "
        "{%0,%1,%2,%3}, {%4,%5,%6,%7}, {%8,%9}, {%0,%1,%2,%3};"
        : "+f"(c[0]), "+f"(c[1]), "+f"(c[2]), "+f"(c[3])
        : "r"(a0), "r"(a1), "r"(a2), "r"(a3), "r"(b0), "r"(b1));
}

// =======================================================================
// K0: emb (fp32) -> g_embh (bf16)
// =======================================================================
__global__ void __launch_bounds__(256)
k_0(const float* __restrict__ emb) {
    int t = blockIdx.x * 256 + threadIdx.x;
    const float4* src = (const float4*)emb;
    float4 a = src[t * 2];
    float4 b = src[t * 2 + 1];
    __nv_bfloat162* dst = (__nv_bfloat162*)g_embh;
    dst[t * 4 + 0] = __floats2bfloat162_rn(a.x, a.y);
    dst[t * 4 + 1] = __floats2bfloat162_rn(a.z, a.w);
    dst[t * 4 + 2] = __floats2bfloat162_rn(b.x, b.y);
    dst[t * 4 + 3] = __floats2bfloat162_rn(b.z, b.w);
}

// =======================================================================
// K1: pack | gather(bf16 emb) | alpha, striped  [unchanged]
// =======================================================================
__global__ void __launch_bounds__(256)
k_1(const int*   __restrict__ adj,
    const int*   __restrict__ nidx,
    const float* __restrict__ tev,
    const float* __restrict__ theta_p) {
    __shared__ int   sdeg[8];
    __shared__ float sw[8];

    int b    = blockIdx.x;
    int tid  = threadIdx.x;
    int lane = tid & 31, w = tid >> 5;

    if (b < 2048 * 3) {
        int r = b % 3, q = b / 3;
        if (r < 2) {
            int row = q * 2 + r;
            const int* a = adj + (size_t)row * NN;
            int v[16];
            #pragma unroll
            for (int i = 0; i < 16; i++)
                v[i] = a[(w * 16 + i) * 32 + lane];
            unsigned keep = 0;
            #pragma unroll
            for (int i = 0; i < 16; i++) {
                unsigned m = __ballot_sync(0xffffffffu, v[i] != 0);
                if (lane == i) keep = m;
            }
            if (lane < 16)
                g_bits[row * NW + w * 16 + lane] = keep;
            int dsum = (lane < 16) ? __popc(keep) : 0;
            #pragma unroll
            for (int o = 16; o; o >>= 1)
                dsum += __shfl_down_sync(0xffffffffu, dsum, o);
            if (lane == 0) sdeg[w] = dsum;
            __syncthreads();
            if (tid == 0) {
                int s = 0;
                #pragma unroll
                for (int i = 0; i < 8; i++) s += sdeg[i];
                float d   = (float)s;
                float den = d * (d - 1.0f);
                if (den == 0.0f) den = 1e-6f;
                g_invden[row] = 2.0f / den;
            }
        } else {
            int unit = q * 8 + w;
            const uint2* e2 = (const uint2*)g_embh;
            int nid = 0;
            if (lane < KK) nid = nidx[unit * KK + lane];
            float4 acc = make_float4(0.f, 0.f, 0.f, 0.f);
            #pragma unroll
            for (int k = 0; k < KK; k++) {
                int id = __shfl_sync(0xffffffffu, nid, k);
                uint2 v = __ldg(&e2[id * 32 + lane]);
                float2 lo = bcvt(v.x), hi = bcvt(v.y);
                acc.x += lo.x; acc.y += lo.y; acc.z += hi.x; acc.w += hi.y;
            }
            ((float4*)g_hbar)[unit * 32 + lane] =
                make_float4(acc.x * 0.0625f, acc.y * 0.0625f,
                            acc.z * 0.0625f, acc.w * 0.0625f);
        }
    } else {
        float th = theta_p[0];
        float s  = 0.f;
        for (int i = tid; i < EE; i += 256)
            s += expf(-th * (1.0f - tev[i]));
        #pragma unroll
        for (int o = 16; o; o >>= 1) s += __shfl_down_sync(0xffffffffu, s, o);
        if (lane == 0) sw[w] = s;
        __syncthreads();
        if (tid == 0) {
            float tot = 0.f;
            #pragma unroll
            for (int i = 0; i < 8; i++) tot += sw[i];
            g_alpha = tot;
        }
    }
}

// =======================================================================
// K2: tri — 2 rows/block, MLP-8 chunks  [unchanged]
// =======================================================================
__global__ void __launch_bounds__(256)
k_tri() {
    __shared__ __align__(16) unsigned sri[2][NW];
    __shared__ int  list[2][192];
    __shared__ int  warpsum[8], warpbase[8];
    __shared__ int  scnt[2];
    __shared__ int  swsum[8];

    int tid  = threadIdx.x;
    int lane = tid & 31, w = tid >> 5;
    int half = w >> 2;
    int wh   = w & 3;
    int th   = tid & 127;
    int i    = blockIdx.x * 2 + half;

    sri[half][th] = g_bits[i * NW + th];
    __syncthreads();

    unsigned word = sri[half][th];
    int c = __popc(word);
    int x = c;
    #pragma unroll
    for (int o = 1; o < 32; o <<= 1) {
        int y = __shfl_up_sync(0xffffffffu, x, o);
        if (lane >= o) x += y;
    }
    if (lane == 31) warpsum[w] = x;
    __syncthreads();
    if (tid < 2) {
        int s = 0;
        #pragma unroll
        for (int k = 0; k < 4; k++) {
            int t = warpsum[tid * 4 + k];
            warpbase[tid * 4 + k] = s;
            s += t;
        }
        scnt[tid] = s;
    }
    __syncthreads();
    {
        int base = warpbase[w] + x - c;
        unsigned ww = word;
        while (ww) {
            int bit = __ffs(ww) - 1;
            ww &= ww - 1;
            list[half][base++] = th * 32 + bit;
        }
    }
    __syncthreads();

    int cnt = scnt[half];
    int cpw = (cnt + 3) >> 2;
    int start = wh * cpw;
    int end   = min(cnt, start + cpw);

    uint4 ri = ((const uint4*)&sri[half][0])[lane];
    const uint4 zz = make_uint4(0u, 0u, 0u, 0u);
    int my = 0;
    for (int p0 = start; p0 < end; p0 += 8) {
        uint4 x0 = zz, x1 = zz, x2 = zz, x3 = zz,
              x4 = zz, x5 = zz, x6 = zz, x7 = zz;
        if (p0 + 0 < end) x0 = ((const uint4*)&g_bits[list[half][p0 + 0] * NW])[lane];
        if (p0 + 1 < end) x1 = ((const uint4*)&g_bits[list[half][p0 + 1] * NW])[lane];
        if (p0 + 2 < end) x2 = ((const uint4*)&g_bits[list[half][p0 + 2] * NW])[lane];
        if (p0 + 3 < end) x3 = ((const uint4*)&g_bits[list[half][p0 + 3] * NW])[lane];
        if (p0 + 4 < end) x4 = ((const uint4*)&g_bits[list[half][p0 + 4] * NW])[lane];
        if (p0 + 5 < end) x5 = ((const uint4*)&g_bits[list[half][p0 + 5] * NW])[lane];
        if (p0 + 6 < end) x6 = ((const uint4*)&g_bits[list[half][p0 + 6] * NW])[lane];
        if (p0 + 7 < end) x7 = ((const uint4*)&g_bits[list[half][p0 + 7] * NW])[lane];
        my += __popc(x0.x & ri.x) + __popc(x0.y & ri.y)
            + __popc(x0.z & ri.z) + __popc(x0.w & ri.w);
        my += __popc(x1.x & ri.x) + __popc(x1.y & ri.y)
            + __popc(x1.z & ri.z) + __popc(x1.w & ri.w);
        my += __popc(x2.x & ri.x) + __popc(x2.y & ri.y)
            + __popc(x2.z & ri.z) + __popc(x2.w & ri.w);
        my += __popc(x3.x & ri.x) + __popc(x3.y & ri.y)
            + __popc(x3.z & ri.z) + __popc(x3.w & ri.w);
        my += __popc(x4.x & ri.x) + __popc(x4.y & ri.y)
            + __popc(x4.z & ri.z) + __popc(x4.w & ri.w);
        my += __popc(x5.x & ri.x) + __popc(x5.y & ri.y)
            + __popc(x5.z & ri.z) + __popc(x5.w & ri.w);
        my += __popc(x6.x & ri.x) + __popc(x6.y & ri.y)
            + __popc(x6.z & ri.z) + __popc(x6.w & ri.w);
        my += __popc(x7.x & ri.x) + __popc(x7.y & ri.y)
            + __popc(x7.z & ri.z) + __popc(x7.w & ri.w);
    }
    #pragma unroll
    for (int o = 16; o; o >>= 1) my += __shfl_down_sync(0xffffffffu, my, o);
    if (lane == 0) swsum[w] = my;
    __syncthreads();
    if ((tid & 127) == 0) {
        int h = tid >> 7;
        int tot = swsum[h * 4 + 0] + swsum[h * 4 + 1]
                + swsum[h * 4 + 2] + swsum[h * 4 + 3];
        g_C[blockIdx.x * 2 + h] = (float)tot * g_invden[blockIdx.x * 2 + h];
    }
}

// =======================================================================
// K3: egemm via tf32 mma — N-split: 16 nodes x 32 cols per block
//     grid = (NN/16) * 4, 128 threads (4 warps x 8 cols)
// =======================================================================
__global__ void __launch_bounds__(128)
k_egemm(const float* __restrict__ Wb,
        const float* __restrict__ bb) {
    __shared__ float sA[16 * 516];           // 33 KB
    int tid  = threadIdx.x;
    int lane = tid & 31, w = tid >> 5;
    int g    = lane >> 2, tig = lane & 3;
    int tile = blockIdx.x >> 2;
    int cg   = blockIdx.x & 3;
    int n0   = tile * 16;
    int colbase = cg * 32 + w * 8;

    for (int idx = tid; idx < 16 * 512; idx += 128) {
        int n = idx >> 9, k = idx & 511;
        sA[n * 516 + k] = __uint_as_float(f2tf(g_hbar[(n0 + n) * 512 + k]));
    }
    __syncthreads();

    float acc[4] = {0.f, 0.f, 0.f, 0.f};
    const unsigned* uA = (const unsigned*)sA;
    int colB = colbase + g;
    #pragma unroll 8
    for (int ks = 0; ks < 64; ks++) {
        int k0 = ks * 8;
        unsigned a0 = uA[g * 516 + k0 + tig];
        unsigned a1 = uA[(g + 8) * 516 + k0 + tig];
        unsigned a2 = uA[g * 516 + k0 + tig + 4];
        unsigned a3 = uA[(g + 8) * 516 + k0 + tig + 4];
        unsigned b0 = f2tf(__ldg(&Wb[(k0 + tig) * DD + colB]));
        unsigned b1 = f2tf(__ldg(&Wb[(k0 + tig + 4) * DD + colB]));
        mma8(acc, a0, a1, a2, a3, b0, b1);
    }

    int e0 = colbase + 2 * tig;
    int e1 = e0 + 1;
    float bs0 = bb[e0] + bb[DD + e0] + bb[2 * DD + e0] + bb[3 * DD + e0];
    float bs1 = bb[e1] + bb[DD + e1] + bb[2 * DD + e1] + bb[3 * DD + e1];
    float h00 = (acc[0] + bs0) * 0.25f;
    float h01 = (acc[1] + bs1) * 0.25f;
    float h10 = (acc[2] + bs0) * 0.25f;
    float h11 = (acc[3] + bs1) * 0.25f;
    g_epsh[(n0 + g) * DD + e0]     = __float2bfloat16(1.0f / (1.0f + expf(-h00)));
    g_epsh[(n0 + g) * DD + e1]     = __float2bfloat16(1.0f / (1.0f + expf(-h01)));
    g_epsh[(n0 + g + 8) * DD + e0] = __float2bfloat16(1.0f / (1.0f + expf(-h10)));
    g_epsh[(n0 + g + 8) * DD + e1] = __float2bfloat16(1.0f / (1.0f + expf(-h11)));
}

// =======================================================================
// K4: proj via tf32 mma — N-split: 16 nodes x 32 cols per block
//     3 type-GEMMs, select at epilogue; grid = (NN/16)*4, 128 threads
// =======================================================================
__global__ void __launch_bounds__(128)
k_proj(const float* __restrict__ emb,
       const float* __restrict__ Wp,
       const int*   __restrict__ ntype) {
    __shared__ float sA[16 * 132];           // 8.4 KB
    __shared__ int   sty[16];
    int tid  = threadIdx.x;
    int lane = tid & 31, w = tid >> 5;
    int g    = lane >> 2, tig = lane & 3;
    int tile = blockIdx.x >> 2;
    int cg   = blockIdx.x & 3;
    int n0   = tile * 16;
    int colbase = cg * 32 + w * 8;

    for (int idx = tid; idx < 16 * DD; idx += 128) {
        int n = idx >> 7, d = idx & 127;
        sA[n * 132 + d] = __uint_as_float(f2tf(emb[(n0 + n) * DD + d]));
    }
    if (tid < 16) sty[tid] = ntype[n0 + tid];
    __syncthreads();

    float acc[3][4];
    #pragma unroll
    for (int t = 0; t < 3; t++)
        #pragma unroll
        for (int q = 0; q < 4; q++) acc[t][q] = 0.f;

    const unsigned* uA = (const unsigned*)sA;
    int colB = colbase + g;
    #pragma unroll 4
    for (int ks = 0; ks < 16; ks++) {
        int k0 = ks * 8;
        unsigned a0 = uA[g * 132 + k0 + tig];
        unsigned a1 = uA[(g + 8) * 132 + k0 + tig];
        unsigned a2 = uA[g * 132 + k0 + tig + 4];
        unsigned a3 = uA[(g + 8) * 132 + k0 + tig + 4];
        #pragma unroll
        for (int t = 0; t < 3; t++) {
            const float* W = Wp + t * DD * DD;
            unsigned b0 = f2tf(__ldg(&W[(k0 + tig) * DD + colB]));
            unsigned b1 = f2tf(__ldg(&W[(k0 + tig + 4) * DD + colB]));
            mma8(acc[t], a0, a1, a2, a3, b0, b1);
        }
    }

    int ty0 = sty[g], ty1 = sty[g + 8];
    int e0 = colbase + 2 * tig;
    int e1 = e0 + 1;
    float v00 = (ty0 == 0) ? acc[0][0] : ((ty0 == 1) ? acc[1][0] : acc[2][0]);
    float v01 = (ty0 == 0) ? acc[0][1] : ((ty0 == 1) ? acc[1][1] : acc[2][1]);
    float v10 = (ty1 == 0) ? acc[0][2] : ((ty1 == 1) ? acc[1][2] : acc[2][2]);
    float v11 = (ty1 == 0) ? acc[0][3] : ((ty1 == 1) ? acc[1][3] : acc[2][3]);
    g_projh[(n0 + g) * DD + e0]     = __float2bfloat16(v00);
    g_projh[(n0 + g) * DD + e1]     = __float2bfloat16(v01);
    g_projh[(n0 + g + 8) * DD + e0] = __float2bfloat16(v10);
    g_projh[(n0 + g + 8) * DD + e1] = __float2bfloat16(v11);
}

// =======================================================================
// K5: per-pair score (warp per pair), bf16 vectors  [unchanged]
// =======================================================================
__global__ void __launch_bounds__(256)
k_pairs(const int*   __restrict__ pairs,
        const float* __restrict__ q1p,
        const float* __restrict__ q2p,
        float*       __restrict__ out) {
    int gw   = (blockIdx.x * blockDim.x + threadIdx.x) >> 5;
    int lane = threadIdx.x & 31;
    if (gw >= PP) return;
    int pm = pairs[gw * 2 + 0];
    int pn = pairs[gw * 2 + 1];

    uint2 ap = __ldg(&((const uint2*)&g_projh[pm * DD])[lane]);
    uint2 bp = __ldg(&((const uint2*)&g_projh[pn * DD])[lane]);
    uint2 am = __ldg(&((const uint2*)&g_embh [pm * DD])[lane]);
    uint2 bm2= __ldg(&((const uint2*)&g_embh [pn * DD])[lane]);
    uint2 ae = __ldg(&((const uint2*)&g_epsh [pm * DD])[lane]);
    uint2 be = __ldg(&((const uint2*)&g_epsh [pn * DD])[lane]);
    uint4 wm = ((const uint4*)&g_bits[pm * NW])[lane];
    uint4 wn = ((const uint4*)&g_bits[pn * NW])[lane];

    float2 a0 = bcvt(ap.x), a1 = bcvt(ap.y);
    float2 b0 = bcvt(bp.x), b1 = bcvt(bp.y);
    float d0 = a0.x - b0.x, d1 = a0.y - b0.y, d2 = a1.x - b1.x, d3 = a1.y - b1.y;
    float s1 = d0*d0 + d1*d1 + d2*d2 + d3*d3;

    float2 m0 = bcvt(am.x), m1 = bcvt(am.y);
    float2 n0 = bcvt(bm2.x), n1 = bcvt(bm2.y);
    float e0 = m0.x - n0.x, e1 = m0.y - n0.y, e2 = m1.x - n1.x, e3 = m1.y - n1.y;
    float s2 = e0*e0 + e1*e1 + e2*e2 + e3*e3;

    float2 p0 = bcvt(ae.x), p1 = bcvt(ae.y);
    float2 r0 = bcvt(be.x), r1 = bcvt(be.y);
    float s3 = p0.x*r0.x + p0.y*r0.y + p1.x*r1.x + p1.y*r1.y;

    float cs = 0.f;
    {
        unsigned ws[4] = { wm.x & wn.x, wm.y & wn.y, wm.z & wn.z, wm.w & wn.w };
        #pragma unroll
        for (int c = 0; c < 4; c++) {
            unsigned word = ws[c];
            int j0 = (lane * 4 + c) * 32;
            while (word) {
                int bpos = __ffs(word) - 1;
                word &= word - 1;
                cs += g_C[j0 + bpos];
            }
        }
    }

    #pragma unroll
    for (int o = 16; o; o >>= 1) {
        s1 += __shfl_xor_sync(0xffffffffu, s1, o);
        s2 += __shfl_xor_sync(0xffffffffu, s2, o);
        s3 += __shfl_xor_sync(0xffffffffu, s3, o);
        cs += __shfl_xor_sync(0xffffffffu, cs, o);
    }

    if (lane == 0) {
        float gamma = -sqrtf(s1);
        float g     = -s2;
        float lamb  = gamma + g_alpha + cs * g + s3 * (1.0f / (float)DD);
        float lam   = expf(lamb);
        float z     = q1p[0] * lam + q2p[0];
        out[gw] = 1.0f / (1.0f + expf(-z));
    }
}

// ---------------- launcher ----------------
extern "C" void kernel_launch(void* const* d_in, const int* in_sizes, int n_in,
                              void* d_out, int out_size) {
    const int*   pairs   = (const int*)  d_in[0];
    const int*   adj     = (const int*)  d_in[1];
    const int*   nidx    = (const int*)  d_in[2];
    const int*   ntype   = (const int*)  d_in[3];
    const float* tev     = (const float*)d_in[4];
    const float* emb     = (const float*)d_in[5];
    const float* Wp      = (const float*)d_in[6];
    const float* Wb      = (const float*)d_in[7];
    const float* bb      = (const float*)d_in[8];
    const float* theta_p = (const float*)d_in[9];
    const float* q1p     = (const float*)d_in[10];
    const float* q2p     = (const float*)d_in[11];
    float*       out     = (float*)d_out;

    k_0    <<<256, 256>>>(emb);
    k_1    <<<GRID_1, 256>>>(adj, nidx, tev, theta_p);
    k_tri  <<<NN / 2, 256>>>();
    k_proj <<<(NN / 16) * 4, 128>>>(emb, Wp, ntype);
    k_egemm<<<(NN / 16) * 4, 128>>>(Wb, bb);
    k_pairs<<<PP / 8, 256>>>(pairs, q1p, q2p, out);
}

// round 17
// speedup vs baseline: 1.2888x; 1.1389x over previous
#include <cuda_runtime.h>
#include <cuda_bf16.h>
#include <cstdint>

// Problem constants
#define NN   4096
#define PP   32768
#define EE   4096
#define DD   128
#define RR   4
#define KK   16
#define NW   128       // 4096 bits / 32 words per adjacency row

// ---- K1 striping: group of 3 = 2 pack rows + 1 gather block; +1 tail ----
#define GRID_1  (2048 * 3 + 1)

// ---------------- device scratch ----------------
__device__ unsigned       g_bits  [NN * NW];
__device__ float          g_C     [NN];
__device__ float          g_invden[NN];
__device__ __nv_bfloat16  g_embh  [NN * DD];      // bf16 copy of emb
__device__ __nv_bfloat16  g_projh [NN * DD];      // bf16 proj
__device__ __nv_bfloat16  g_epsh  [NN * DD];      // bf16 eps
__device__ float          g_hbar  [NN * RR * DD]; // fp32 h_bar
__device__ float          g_alpha;

// ---------------- helpers ----------------
__device__ __forceinline__ float2 bcvt(unsigned u) {
    __nv_bfloat162 h = *reinterpret_cast<__nv_bfloat162*>(&u);
    return __bfloat1622float2(h);
}
__device__ __forceinline__ unsigned f2tf(float x) {
    unsigned r;
    asm("cvt.rna.tf32.f32 %0, %1;" : "=r"(r) : "f"(x));
    return r;
}
// mma.m16n8k8 tf32: D += A*B  (fp32 accum in place)
__device__ __forceinline__ void mma8(float* c,
                                     unsigned a0, unsigned a1,
                                     unsigned a2, unsigned a3,
                                     unsigned b0, unsigned b1) {
    asm volatile(
        "mma.sync.aligned.m16n8k8.row.col.f32.tf32.tf32.f32 "
        "{%0,%1,%2,%3}, {%4,%5,%6,%7}, {%8,%9}, {%0,%1,%2,%3};"
        : "+f"(c[0]), "+f"(c[1]), "+f"(c[2]), "+f"(c[3])
        : "r"(a0), "r"(a1), "r"(a2), "r"(a3), "r"(b0), "r"(b1));
}
__device__ __forceinline__ void st_tf4(float* dst, float4 v) {
    dst[0] = __uint_as_float(f2tf(v.x));
    dst[1] = __uint_as_float(f2tf(v.y));
    dst[2] = __uint_as_float(f2tf(v.z));
    dst[3] = __uint_as_float(f2tf(v.w));
}

// =======================================================================
// K0: emb (fp32) -> g_embh (bf16)
// =======================================================================
__global__ void __launch_bounds__(256)
k_0(const float* __restrict__ emb) {
    int t = blockIdx.x * 256 + threadIdx.x;
    const float4* src = (const float4*)emb;
    float4 a = src[t * 2];
    float4 b = src[t * 2 + 1];
    __nv_bfloat162* dst = (__nv_bfloat162*)g_embh;
    dst[t * 4 + 0] = __floats2bfloat162_rn(a.x, a.y);
    dst[t * 4 + 1] = __floats2bfloat162_rn(a.z, a.w);
    dst[t * 4 + 2] = __floats2bfloat162_rn(b.x, b.y);
    dst[t * 4 + 3] = __floats2bfloat162_rn(b.z, b.w);
}

// =======================================================================
// K1: pack | gather(bf16 emb) | alpha, striped  [unchanged]
// =======================================================================
__global__ void __launch_bounds__(256)
k_1(const int*   __restrict__ adj,
    const int*   __restrict__ nidx,
    const float* __restrict__ tev,
    const float* __restrict__ theta_p) {
    __shared__ int   sdeg[8];
    __shared__ float sw[8];

    int b    = blockIdx.x;
    int tid  = threadIdx.x;
    int lane = tid & 31, w = tid >> 5;

    if (b < 2048 * 3) {
        int r = b % 3, q = b / 3;
        if (r < 2) {
            int row = q * 2 + r;
            const int* a = adj + (size_t)row * NN;
            int v[16];
            #pragma unroll
            for (int i = 0; i < 16; i++)
                v[i] = a[(w * 16 + i) * 32 + lane];
            unsigned keep = 0;
            #pragma unroll
            for (int i = 0; i < 16; i++) {
                unsigned m = __ballot_sync(0xffffffffu, v[i] != 0);
                if (lane == i) keep = m;
            }
            if (lane < 16)
                g_bits[row * NW + w * 16 + lane] = keep;
            int dsum = (lane < 16) ? __popc(keep) : 0;
            #pragma unroll
            for (int o = 16; o; o >>= 1)
                dsum += __shfl_down_sync(0xffffffffu, dsum, o);
            if (lane == 0) sdeg[w] = dsum;
            __syncthreads();
            if (tid == 0) {
                int s = 0;
                #pragma unroll
                for (int i = 0; i < 8; i++) s += sdeg[i];
                float d   = (float)s;
                float den = d * (d - 1.0f);
                if (den == 0.0f) den = 1e-6f;
                g_invden[row] = 2.0f / den;
            }
        } else {
            int unit = q * 8 + w;
            const uint2* e2 = (const uint2*)g_embh;
            int nid = 0;
            if (lane < KK) nid = nidx[unit * KK + lane];
            float4 acc = make_float4(0.f, 0.f, 0.f, 0.f);
            #pragma unroll
            for (int k = 0; k < KK; k++) {
                int id = __shfl_sync(0xffffffffu, nid, k);
                uint2 v = __ldg(&e2[id * 32 + lane]);
                float2 lo = bcvt(v.x), hi = bcvt(v.y);
                acc.x += lo.x; acc.y += lo.y; acc.z += hi.x; acc.w += hi.y;
            }
            ((float4*)g_hbar)[unit * 32 + lane] =
                make_float4(acc.x * 0.0625f, acc.y * 0.0625f,
                            acc.z * 0.0625f, acc.w * 0.0625f);
        }
    } else {
        float th = theta_p[0];
        float s  = 0.f;
        for (int i = tid; i < EE; i += 256)
            s += expf(-th * (1.0f - tev[i]));
        #pragma unroll
        for (int o = 16; o; o >>= 1) s += __shfl_down_sync(0xffffffffu, s, o);
        if (lane == 0) sw[w] = s;
        __syncthreads();
        if (tid == 0) {
            float tot = 0.f;
            #pragma unroll
            for (int i = 0; i < 8; i++) tot += sw[i];
            g_alpha = tot;
        }
    }
}

// =======================================================================
// K2: tri — 2 rows/block, MLP-8 chunks  [unchanged]
// =======================================================================
__global__ void __launch_bounds__(256)
k_tri() {
    __shared__ __align__(16) unsigned sri[2][NW];
    __shared__ int  list[2][192];
    __shared__ int  warpsum[8], warpbase[8];
    __shared__ int  scnt[2];
    __shared__ int  swsum[8];

    int tid  = threadIdx.x;
    int lane = tid & 31, w = tid >> 5;
    int half = w >> 2;
    int wh   = w & 3;
    int th   = tid & 127;
    int i    = blockIdx.x * 2 + half;

    sri[half][th] = g_bits[i * NW + th];
    __syncthreads();

    unsigned word = sri[half][th];
    int c = __popc(word);
    int x = c;
    #pragma unroll
    for (int o = 1; o < 32; o <<= 1) {
        int y = __shfl_up_sync(0xffffffffu, x, o);
        if (lane >= o) x += y;
    }
    if (lane == 31) warpsum[w] = x;
    __syncthreads();
    if (tid < 2) {
        int s = 0;
        #pragma unroll
        for (int k = 0; k < 4; k++) {
            int t = warpsum[tid * 4 + k];
            warpbase[tid * 4 + k] = s;
            s += t;
        }
        scnt[tid] = s;
    }
    __syncthreads();
    {
        int base = warpbase[w] + x - c;
        unsigned ww = word;
        while (ww) {
            int bit = __ffs(ww) - 1;
            ww &= ww - 1;
            list[half][base++] = th * 32 + bit;
        }
    }
    __syncthreads();

    int cnt = scnt[half];
    int cpw = (cnt + 3) >> 2;
    int start = wh * cpw;
    int end   = min(cnt, start + cpw);

    uint4 ri = ((const uint4*)&sri[half][0])[lane];
    const uint4 zz = make_uint4(0u, 0u, 0u, 0u);
    int my = 0;
    for (int p0 = start; p0 < end; p0 += 8) {
        uint4 x0 = zz, x1 = zz, x2 = zz, x3 = zz,
              x4 = zz, x5 = zz, x6 = zz, x7 = zz;
        if (p0 + 0 < end) x0 = ((const uint4*)&g_bits[list[half][p0 + 0] * NW])[lane];
        if (p0 + 1 < end) x1 = ((const uint4*)&g_bits[list[half][p0 + 1] * NW])[lane];
        if (p0 + 2 < end) x2 = ((const uint4*)&g_bits[list[half][p0 + 2] * NW])[lane];
        if (p0 + 3 < end) x3 = ((const uint4*)&g_bits[list[half][p0 + 3] * NW])[lane];
        if (p0 + 4 < end) x4 = ((const uint4*)&g_bits[list[half][p0 + 4] * NW])[lane];
        if (p0 + 5 < end) x5 = ((const uint4*)&g_bits[list[half][p0 + 5] * NW])[lane];
        if (p0 + 6 < end) x6 = ((const uint4*)&g_bits[list[half][p0 + 6] * NW])[lane];
        if (p0 + 7 < end) x7 = ((const uint4*)&g_bits[list[half][p0 + 7] * NW])[lane];
        my += __popc(x0.x & ri.x) + __popc(x0.y & ri.y)
            + __popc(x0.z & ri.z) + __popc(x0.w & ri.w);
        my += __popc(x1.x & ri.x) + __popc(x1.y & ri.y)
            + __popc(x1.z & ri.z) + __popc(x1.w & ri.w);
        my += __popc(x2.x & ri.x) + __popc(x2.y & ri.y)
            + __popc(x2.z & ri.z) + __popc(x2.w & ri.w);
        my += __popc(x3.x & ri.x) + __popc(x3.y & ri.y)
            + __popc(x3.z & ri.z) + __popc(x3.w & ri.w);
        my += __popc(x4.x & ri.x) + __popc(x4.y & ri.y)
            + __popc(x4.z & ri.z) + __popc(x4.w & ri.w);
        my += __popc(x5.x & ri.x) + __popc(x5.y & ri.y)
            + __popc(x5.z & ri.z) + __popc(x5.w & ri.w);
        my += __popc(x6.x & ri.x) + __popc(x6.y & ri.y)
            + __popc(x6.z & ri.z) + __popc(x6.w & ri.w);
        my += __popc(x7.x & ri.x) + __popc(x7.y & ri.y)
            + __popc(x7.z & ri.z) + __popc(x7.w & ri.w);
    }
    #pragma unroll
    for (int o = 16; o; o >>= 1) my += __shfl_down_sync(0xffffffffu, my, o);
    if (lane == 0) swsum[w] = my;
    __syncthreads();
    if ((tid & 127) == 0) {
        int h = tid >> 7;
        int tot = swsum[h * 4 + 0] + swsum[h * 4 + 1]
                + swsum[h * 4 + 2] + swsum[h * 4 + 3];
        g_C[blockIdx.x * 2 + h] = (float)tot * g_invden[blockIdx.x * 2 + h];
    }
}

// =======================================================================
// K3: egemm — smem-tiled tf32 mma: 32 nodes x 32 cols, K chunks of 64
//     256 thr = 8 warps (2 m-tiles x 4 col-groups); all frag loads via LDS
// =======================================================================
__global__ void __launch_bounds__(256)
k_egemm(const float* __restrict__ Wb,
        const float* __restrict__ bb) {
    __shared__ float sA[32 * 68];    // 8.7 KB, stride 68 (banks 4g+tig)
    __shared__ float sB[64 * 40];    // 10.0 KB, stride 40 (banks 8*rel)
    int tid  = threadIdx.x;
    int lane = tid & 31, w = tid >> 5;
    int g    = lane >> 2, tig = lane & 3;
    int mt   = w >> 2, cg = w & 3;
    int tile = blockIdx.x >> 2, cq = blockIdx.x & 3;
    int n0   = tile * 32, c0 = cq * 32;

    float acc[4] = {0.f, 0.f, 0.f, 0.f};

    for (int kc = 0; kc < 8; kc++) {
        // stage A [32 x 64] (coalesced float4, tf32 on store)
        #pragma unroll
        for (int rpt = 0; rpt < 2; rpt++) {
            int idx = rpt * 256 + tid;           // 0..511
            int n = idx >> 4, kq = idx & 15;
            float4 v = ((const float4*)&g_hbar[(n0 + n) * 512 + kc * 64])[kq];
            st_tf4(&sA[n * 68 + kq * 4], v);
        }
        // stage B [64 x 32]
        #pragma unroll
        for (int rpt = 0; rpt < 2; rpt++) {
            int idx = rpt * 256 + tid;           // 0..511
            int k = idx >> 3, cf = idx & 7;
            float4 v = ((const float4*)&Wb[(kc * 64 + k) * DD + c0])[cf];
            st_tf4(&sB[k * 40 + cf * 4], v);
        }
        __syncthreads();
        const unsigned* uA = (const unsigned*)sA;
        const unsigned* uB = (const unsigned*)sB;
        #pragma unroll
        for (int ks = 0; ks < 8; ks++) {
            int k0 = ks * 8;
            unsigned a0 = uA[(mt * 16 + g) * 68 + k0 + tig];
            unsigned a1 = uA[(mt * 16 + g + 8) * 68 + k0 + tig];
            unsigned a2 = uA[(mt * 16 + g) * 68 + k0 + tig + 4];
            unsigned a3 = uA[(mt * 16 + g + 8) * 68 + k0 + tig + 4];
            unsigned b0 = uB[(k0 + tig) * 40 + cg * 8 + g];
            unsigned b1 = uB[(k0 + tig + 4) * 40 + cg * 8 + g];
            mma8(acc, a0, a1, a2, a3, b0, b1);
        }
        __syncthreads();
    }

    int e0 = c0 + cg * 8 + 2 * tig, e1 = e0 + 1;
    int row0 = n0 + mt * 16 + g, row1 = row0 + 8;
    float bs0 = bb[e0] + bb[DD + e0] + bb[2 * DD + e0] + bb[3 * DD + e0];
    float bs1 = bb[e1] + bb[DD + e1] + bb[2 * DD + e1] + bb[3 * DD + e1];
    float h00 = (acc[0] + bs0) * 0.25f;
    float h01 = (acc[1] + bs1) * 0.25f;
    float h10 = (acc[2] + bs0) * 0.25f;
    float h11 = (acc[3] + bs1) * 0.25f;
    g_epsh[row0 * DD + e0] = __float2bfloat16(1.0f / (1.0f + expf(-h00)));
    g_epsh[row0 * DD + e1] = __float2bfloat16(1.0f / (1.0f + expf(-h01)));
    g_epsh[row1 * DD + e0] = __float2bfloat16(1.0f / (1.0f + expf(-h10)));
    g_epsh[row1 * DD + e1] = __float2bfloat16(1.0f / (1.0f + expf(-h11)));
}

// =======================================================================
// K4: proj — smem-tiled tf32 mma: 32 nodes x 32 cols, 3 type-GEMMs
//     A staged once (K=128); B re-staged per type
// =======================================================================
__global__ void __launch_bounds__(256)
k_proj(const float* __restrict__ emb,
       const float* __restrict__ Wp,
       const int*   __restrict__ ntype) {
    __shared__ float sA[32 * 132];   // 16.9 KB
    __shared__ float sB[128 * 40];   // 20.0 KB
    __shared__ int   sty[32];
    int tid  = threadIdx.x;
    int lane = tid & 31, w = tid >> 5;
    int g    = lane >> 2, tig = lane & 3;
    int mt   = w >> 2, cg = w & 3;
    int tile = blockIdx.x >> 2, cq = blockIdx.x & 3;
    int n0   = tile * 32, c0 = cq * 32;

    // stage A [32 x 128] once
    #pragma unroll
    for (int rpt = 0; rpt < 4; rpt++) {
        int idx = rpt * 256 + tid;               // 0..1023
        int n = idx >> 5, kq = idx & 31;
        float4 v = ((const float4*)&emb[(n0 + n) * DD])[kq];
        st_tf4(&sA[n * 132 + kq * 4], v);
    }
    if (tid < 32) sty[tid] = ntype[n0 + tid];

    float acc[3][4];
    #pragma unroll
    for (int t = 0; t < 3; t++)
        #pragma unroll
        for (int q = 0; q < 4; q++) acc[t][q] = 0.f;

    const unsigned* uA = (const unsigned*)sA;
    const unsigned* uB = (const unsigned*)sB;

    for (int t = 0; t < 3; t++) {
        __syncthreads();                          // protect prior sB reads (and A stage @ t=0)
        const float* W = Wp + t * DD * DD;
        #pragma unroll
        for (int rpt = 0; rpt < 4; rpt++) {
            int idx = rpt * 256 + tid;           // 0..1023
            int k = idx >> 3, cf = idx & 7;
            float4 v = ((const float4*)&W[k * DD + c0])[cf];
            st_tf4(&sB[k * 40 + cf * 4], v);
        }
        __syncthreads();
        #pragma unroll
        for (int ks = 0; ks < 16; ks++) {
            int k0 = ks * 8;
            unsigned a0 = uA[(mt * 16 + g) * 132 + k0 + tig];
            unsigned a1 = uA[(mt * 16 + g + 8) * 132 + k0 + tig];
            unsigned a2 = uA[(mt * 16 + g) * 132 + k0 + tig + 4];
            unsigned a3 = uA[(mt * 16 + g + 8) * 132 + k0 + tig + 4];
            unsigned b0 = uB[(k0 + tig) * 40 + cg * 8 + g];
            unsigned b1 = uB[(k0 + tig + 4) * 40 + cg * 8 + g];
            mma8(acc[t], a0, a1, a2, a3, b0, b1);
        }
    }

    int row0l = mt * 16 + g, row1l = row0l + 8;
    int ty0 = sty[row0l], ty1 = sty[row1l];
    int e0 = c0 + cg * 8 + 2 * tig, e1 = e0 + 1;
    float v00 = (ty0 == 0) ? acc[0][0] : ((ty0 == 1) ? acc[1][0] : acc[2][0]);
    float v01 = (ty0 == 0) ? acc[0][1] : ((ty0 == 1) ? acc[1][1] : acc[2][1]);
    float v10 = (ty1 == 0) ? acc[0][2] : ((ty1 == 1) ? acc[1][2] : acc[2][2]);
    float v11 = (ty1 == 0) ? acc[0][3] : ((ty1 == 1) ? acc[1][3] : acc[2][3]);
    g_projh[(n0 + row0l) * DD + e0] = __float2bfloat16(v00);
    g_projh[(n0 + row0l) * DD + e1] = __float2bfloat16(v01);
    g_projh[(n0 + row1l) * DD + e0] = __float2bfloat16(v10);
    g_projh[(n0 + row1l) * DD + e1] = __float2bfloat16(v11);
}

// =======================================================================
// K5: per-pair score (warp per pair), bf16 vectors  [unchanged]
// =======================================================================
__global__ void __launch_bounds__(256)
k_pairs(const int*   __restrict__ pairs,
        const float* __restrict__ q1p,
        const float* __restrict__ q2p,
        float*       __restrict__ out) {
    int gw   = (blockIdx.x * blockDim.x + threadIdx.x) >> 5;
    int lane = threadIdx.x & 31;
    if (gw >= PP) return;
    int pm = pairs[gw * 2 + 0];
    int pn = pairs[gw * 2 + 1];

    uint2 ap = __ldg(&((const uint2*)&g_projh[pm * DD])[lane]);
    uint2 bp = __ldg(&((const uint2*)&g_projh[pn * DD])[lane]);
    uint2 am = __ldg(&((const uint2*)&g_embh [pm * DD])[lane]);
    uint2 bm2= __ldg(&((const uint2*)&g_embh [pn * DD])[lane]);
    uint2 ae = __ldg(&((const uint2*)&g_epsh [pm * DD])[lane]);
    uint2 be = __ldg(&((const uint2*)&g_epsh [pn * DD])[lane]);
    uint4 wm = ((const uint4*)&g_bits[pm * NW])[lane];
    uint4 wn = ((const uint4*)&g_bits[pn * NW])[lane];

    float2 a0 = bcvt(ap.x), a1 = bcvt(ap.y);
    float2 b0 = bcvt(bp.x), b1 = bcvt(bp.y);
    float d0 = a0.x - b0.x, d1 = a0.y - b0.y, d2 = a1.x - b1.x, d3 = a1.y - b1.y;
    float s1 = d0*d0 + d1*d1 + d2*d2 + d3*d3;

    float2 m0 = bcvt(am.x), m1 = bcvt(am.y);
    float2 n0 = bcvt(bm2.x), n1 = bcvt(bm2.y);
    float e0 = m0.x - n0.x, e1 = m0.y - n0.y, e2 = m1.x - n1.x, e3 = m1.y - n1.y;
    float s2 = e0*e0 + e1*e1 + e2*e2 + e3*e3;

    float2 p0 = bcvt(ae.x), p1 = bcvt(ae.y);
    float2 r0 = bcvt(be.x), r1 = bcvt(be.y);
    float s3 = p0.x*r0.x + p0.y*r0.y + p1.x*r1.x + p1.y*r1.y;

    float cs = 0.f;
    {
        unsigned ws[4] = { wm.x & wn.x, wm.y & wn.y, wm.z & wn.z, wm.w & wn.w };
        #pragma unroll
        for (int c = 0; c < 4; c++) {
            unsigned word = ws[c];
            int j0 = (lane * 4 + c) * 32;
            while (word) {
                int bpos = __ffs(word) - 1;
                word &= word - 1;
                cs += g_C[j0 + bpos];
            }
        }
    }

    #pragma unroll
    for (int o = 16; o; o >>= 1) {
        s1 += __shfl_xor_sync(0xffffffffu, s1, o);
        s2 += __shfl_xor_sync(0xffffffffu, s2, o);
        s3 += __shfl_xor_sync(0xffffffffu, s3, o);
        cs += __shfl_xor_sync(0xffffffffu, cs, o);
    }

    if (lane == 0) {
        float gamma = -sqrtf(s1);
        float g     = -s2;
        float lamb  = gamma + g_alpha + cs * g + s3 * (1.0f / (float)DD);
        float lam   = expf(lamb);
        float z     = q1p[0] * lam + q2p[0];
        out[gw] = 1.0f / (1.0f + expf(-z));
    }
}

// ---------------- launcher ----------------
extern "C" void kernel_launch(void* const* d_in, const int* in_sizes, int n_in,
                              void* d_out, int out_size) {
    const int*   pairs   = (const int*)  d_in[0];
    const int*   adj     = (const int*)  d_in[1];
    const int*   nidx    = (const int*)  d_in[2];
    const int*   ntype   = (const int*)  d_in[3];
    const float* tev     = (const float*)d_in[4];
    const float* emb     = (const float*)d_in[5];
    const float* Wp      = (const float*)d_in[6];
    const float* Wb      = (const float*)d_in[7];
    const float* bb      = (const float*)d_in[8];
    const float* theta_p = (const float*)d_in[9];
    const float* q1p     = (const float*)d_in[10];
    const float* q2p     = (const float*)d_in[11];
    float*       out     = (float*)d_out;

    k_0    <<<256, 256>>>(emb);
    k_1    <<<GRID_1, 256>>>(adj, nidx, tev, theta_p);
    k_tri  <<<NN / 2, 256>>>();
    k_proj <<<(NN / 32) * 4, 256>>>(emb, Wp, ntype);
    k_egemm<<<(NN / 32) * 4, 256>>>(Wb, bb);
    k_pairs<<<PP / 8, 256>>>(pairs, q1p, q2p, out);
}